// round 9
// baseline (speedup 1.0000x reference)
#include <cuda_runtime.h>
#include <cuda_fp16.h>
#include <cstdint>
#include <math.h>

// Problem constants: B=64, T=512, K=512, H=512. M = B*T = 32768.
#define BB   64
#define TT   512
#define KK   512
#define HH   512
#define MM   (BB * TT)          // 32768

// ---------------------------------------------------------------------------
// Scratch (__device__ globals; no allocations allowed)
// ---------------------------------------------------------------------------
__device__ __half g_xs[(size_t)MM * KK];             // x in fp16
__device__ __half g_ws[3ull * HH * KK];              // W^T in fp16: [w][n][k]

// ---------------------------------------------------------------------------
// Helpers (sm_80-compatible PTX: ldmatrix / mma.sync / cp.async)
// ---------------------------------------------------------------------------
__device__ __forceinline__ uint32_t smem_u32(const void* p) {
    uint32_t a;
    asm("{ .reg .u64 t; cvta.to.shared.u64 t, %1; cvt.u32.u64 %0, t; }" : "=r"(a) : "l"(p));
    return a;
}

__device__ __forceinline__ void cpa16(uint32_t saddr, const void* g) {
    asm volatile("cp.async.cg.shared.global [%0], [%1], 16;" :: "r"(saddr), "l"(g));
}
#define CP_COMMIT() asm volatile("cp.async.commit_group;" ::: "memory")
template <int N>
__device__ __forceinline__ void cp_wait() {
    asm volatile("cp.async.wait_group %0;" :: "n"(N) : "memory");
}

__device__ __forceinline__ void ldsm_x4(uint32_t* r, uint32_t addr) {
    asm volatile("ldmatrix.sync.aligned.m8n8.x4.shared.b16 {%0,%1,%2,%3}, [%4];"
                 : "=r"(r[0]), "=r"(r[1]), "=r"(r[2]), "=r"(r[3]) : "r"(addr));
}
__device__ __forceinline__ void mma_f16(float* d, const uint32_t* a, const uint32_t* b) {
    asm volatile(
        "mma.sync.aligned.m16n8k16.row.col.f32.f16.f16.f32 "
        "{%0,%1,%2,%3}, {%4,%5,%6,%7}, {%8,%9}, {%0,%1,%2,%3};"
        : "+f"(d[0]), "+f"(d[1]), "+f"(d[2]), "+f"(d[3])
        : "r"(a[0]), "r"(a[1]), "r"(a[2]), "r"(a[3]), "r"(b[0]), "r"(b[1]));
}

// Single-MUFU tanh; sigmoid via exact identity s(x) = 0.5*tanh(x/2) + 0.5.
__device__ __forceinline__ float tanh_approx(float x) {
    float y;
    asm("tanh.approx.f32 %0, %1;" : "=f"(y) : "f"(x));
    return y;
}

// ---------------------------------------------------------------------------
// Convert x: linear fp32 -> fp16. 8 elements / thread.
// ---------------------------------------------------------------------------
__global__ void cvt_x_kernel(const float* __restrict__ x) {
    size_t i = ((size_t)blockIdx.x * blockDim.x + threadIdx.x) * 8;
    float4 v0 = *(const float4*)(x + i);
    float4 v1 = *(const float4*)(x + i + 4);
    __half2 h[4];
    h[0] = __floats2half2_rn(v0.x, v0.y);
    h[1] = __floats2half2_rn(v0.z, v0.w);
    h[2] = __floats2half2_rn(v1.x, v1.y);
    h[3] = __floats2half2_rn(v1.z, v1.w);
    *(uint4*)(g_xs + i) = *(uint4*)h;
}

// ---------------------------------------------------------------------------
// Convert weights with coalesced smem transpose: W[k][n] -> W^T[w][n][k] fp16.
// ---------------------------------------------------------------------------
__global__ void cvt_w_kernel(const float* __restrict__ kz,
                             const float* __restrict__ kr,
                             const float* __restrict__ kh) {
    __shared__ float tile[32][33];
    const int w  = blockIdx.z;
    const int k0 = blockIdx.x * 32;
    const int n0 = blockIdx.y * 32;
    const int tx = threadIdx.x, ty = threadIdx.y;
    const float* __restrict__ W = (w == 0) ? kz : (w == 1) ? kr : kh;

    #pragma unroll
    for (int r = 0; r < 4; r++)
        tile[ty + r * 8][tx] = W[(size_t)(k0 + ty + r * 8) * HH + n0 + tx];
    __syncthreads();

    #pragma unroll
    for (int r = 0; r < 4; r++) {
        int n = n0 + ty + r * 8;
        int k = k0 + tx;
        g_ws[((size_t)w * HH + n) * KK + k] = __float2half_rn(tile[tx][ty + r * 8]);
    }
}

// ---------------------------------------------------------------------------
// FUSED GEMM + SCAN. One CTA per (batch b, h-half of 256 channels): 128 CTAs,
// 256 threads, single wave. Per 64-t chunk: 24 pipelined MMA steps
// (3 weights x 8 k-tiles of 64) produce proj[3][64t][256h] fp16 in smem
// (row stride 544B = +32B pad, bank-spread); then 64 scan steps consume it
// directly from smem. Projections NEVER touch DRAM (saves 192 MB round trip
// + the separate 52us scan kernel). Weights stream from L2 each chunk.
// ---------------------------------------------------------------------------
#define TCH     64                      // t per chunk
#define NCHUNK  (TT / TCH)              // 8
#define NSTEP   24                      // (w,ktile) steps per chunk
#define TOTS    (NCHUNK * NSTEP)        // 192

#define X_STG   (TCH * 64 * 2)          // 8192 B   (64 t-rows x 128 B)
#define B_STG   (256 * 64 * 2)          // 32768 B  (256 n-rows x 128 B)
#define SM_X    0                       // 3 slots: 24576 B
#define SM_B    (3 * X_STG)             // 3 slots: 98304 B
#define SM_PROJ (SM_B + 3 * B_STG)      // 122880
#define PROJ_STRIDE 544                 // 256 halfs + 32B pad (8-bank row shift)
#define PROJ_W_BYTES (TCH * PROJ_STRIDE)        // 34816
#define FSMEM   (SM_PROJ + 3 * PROJ_W_BYTES)    // 227328 <= 232448 (227KB)

__global__ __launch_bounds__(256, 1)
void brc_fused(const float* __restrict__ h0,
               const float* __restrict__ mz,
               const float* __restrict__ mr,
               const float* __restrict__ bz,
               const float* __restrict__ br,
               float* __restrict__ out)
{
    extern __shared__ char smem[];
    const uint32_t sbase = smem_u32(smem);
    const int tid  = threadIdx.x;
    const int lane = tid & 31;
    const int wid  = tid >> 5;
    const int wm   = wid & 1;           // m group (2 x 32 rows)
    const int wn   = wid >> 1;          // n group (4 x 64 cols)

    const int b  = blockIdx.x >> 1;
    const int n0 = (blockIdx.x & 1) * 256;

    // ---- scan state (per-thread channel) ----
    const int hch = n0 + tid;
    float hc        = h0[b * HH + hch];
    const float vmz = mz[hch];
    const float vmr = mr[hch];
    const float vbz = bz[hch];
    const float vbr = br[hch];

    const __half* __restrict__ Ap = g_xs + (size_t)b * TT * KK;

    // ---- pipelined loader: step S -> (chunk, w, ktile) ----
    auto load_step = [&](int S, int slot) {
        const int c  = S / NSTEP;
        const int wi = (S % NSTEP) >> 3;
        const int kt = S & 7;
        const int kb = kt * 64;
        const uint32_t sx = sbase + SM_X + slot * X_STG;
        const uint32_t sb = sbase + SM_B + slot * B_STG;
        const __half* xrow = Ap + (size_t)(c * TCH) * KK + kb;
        const __half* brow = g_ws + ((size_t)wi * HH + n0) * KK + kb;
        // X: 64 rows x 8 chunks = 512; 2 per thread
        #pragma unroll
        for (int q = 0; q < 2; q++) {
            int j = tid + q * 256;
            int row = j >> 3, cc = j & 7;
            cpa16(sx + row * 128 + ((cc ^ (row & 7)) * 16),
                  xrow + (size_t)row * KK + cc * 8);
        }
        // B: 256 rows x 8 chunks = 2048; 8 per thread
        #pragma unroll
        for (int q = 0; q < 8; q++) {
            int j = tid + q * 256;
            int row = j >> 3, cc = j & 7;
            cpa16(sb + row * 128 + ((cc ^ (row & 7)) * 16),
                  brow + (size_t)row * KK + cc * 8);
        }
    };

    load_step(0, 0); CP_COMMIT();
    load_step(1, 1); CP_COMMIT();

    float acc[2][8][4];
    #pragma unroll
    for (int i = 0; i < 2; i++)
        #pragma unroll
        for (int j = 0; j < 8; j++)
            #pragma unroll
            for (int q = 0; q < 4; q++) acc[i][j][q] = 0.0f;

    // ldmatrix lane geometry (identical mapping to the proven R8 kernel)
    const int a_r = lane & 15;
    const int a_c = lane >> 4;
    const int b_r = lane & 7;
    const int b_c = (lane >> 3) & 1;
    const int b_g = (lane >> 4) & 1;
    const int er  = lane >> 2;
    const int ec  = (lane & 3) * 2;

    int sl = 0;                                  // slot of step S (mod 3)
    for (int S = 0; S < TOTS; S++) {
        cp_wait<1>();                            // step S copies complete
        __syncthreads();                         // visible to all; all done S-1

        if (S + 2 < TOTS) {                      // refill slot used by S-1
            int ps = sl + 2; if (ps >= 3) ps -= 3;
            load_step(S + 2, ps);
        }
        CP_COMMIT();                             // keep group FIFO count stable

        const uint32_t sx = sbase + SM_X + sl * X_STG;
        const uint32_t sb = sbase + SM_B + sl * B_STG;

        #pragma unroll
        for (int ks = 0; ks < 4; ks++) {
            uint32_t afr[2][4], bfr[8][2];
            #pragma unroll
            for (int mi = 0; mi < 2; mi++) {
                int row = wm * 32 + mi * 16 + a_r;
                int c   = ks * 2 + a_c;
                ldsm_x4(afr[mi], sx + row * 128 + ((c ^ (row & 7)) * 16));
            }
            #pragma unroll
            for (int np = 0; np < 4; np++) {
                int row = wn * 64 + (np * 2 + b_g) * 8 + b_r;
                int c   = ks * 2 + b_c;
                ldsm_x4(&bfr[np * 2][0], sb + row * 128 + ((c ^ (row & 7)) * 16));
            }
            #pragma unroll
            for (int mi = 0; mi < 2; mi++)
                #pragma unroll
                for (int ni = 0; ni < 8; ni++)
                    mma_f16(acc[mi][ni], afr[mi], bfr[ni]);
        }
        if (++sl == 3) sl = 0;

        if ((S & 7) == 7) {                      // epilogue for weight wi
            const int wi = (S % NSTEP) >> 3;
            char* pw = smem + SM_PROJ + wi * PROJ_W_BYTES;
            #pragma unroll
            for (int mi = 0; mi < 2; mi++) {
                #pragma unroll
                for (int ni = 0; ni < 8; ni++) {
                    int gr = wm * 32 + mi * 16 + er;      // t row in chunk
                    int gc = wn * 64 + ni * 8 + ec;       // h col
                    *(__half2*)(pw + gr * PROJ_STRIDE + gc * 2) =
                        __floats2half2_rn(acc[mi][ni][0], acc[mi][ni][1]);
                    *(__half2*)(pw + (gr + 8) * PROJ_STRIDE + gc * 2) =
                        __floats2half2_rn(acc[mi][ni][2], acc[mi][ni][3]);
                    acc[mi][ni][0] = 0.0f; acc[mi][ni][1] = 0.0f;
                    acc[mi][ni][2] = 0.0f; acc[mi][ni][3] = 0.0f;
                }
            }
        }

        if ((S % NSTEP) == NSTEP - 1) {          // chunk done -> scan it
            __syncthreads();                     // proj writes visible
            const int c  = S / NSTEP;
            const char* p0 = smem + SM_PROJ + 0 * PROJ_W_BYTES + tid * 2;
            const char* p1 = smem + SM_PROJ + 1 * PROJ_W_BYTES + tid * 2;
            const char* p2 = smem + SM_PROJ + 2 * PROJ_W_BYTES + tid * 2;
            float* op = out + ((size_t)b * TT + c * TCH) * HH + hch;
            #pragma unroll 4
            for (int t = 0; t < TCH; t++) {
                float az = __half2float(*(const __half*)(p0 + t * PROJ_STRIDE)) + vbz;
                float ar = __half2float(*(const __half*)(p1 + t * PROJ_STRIDE)) + vbr;
                float ah = __half2float(*(const __half*)(p2 + t * PROJ_STRIDE));
                float r  = tanh_approx(fmaf(hc, vmr, ar)) + 1.0f;
                float zg = fmaf(0.5f, tanh_approx(0.5f * fmaf(hc, vmz, az)), 0.5f);
                float cd = tanh_approx(fmaf(r, hc, ah));
                hc = fmaf(zg, hc - cd, cd);
                op[(size_t)t * HH] = hc;
            }
            // next epilogue is >=8 steps away; its loop-top __syncthreads
            // orders this scan before any proj overwrite.
        }
    }
}

// ---------------------------------------------------------------------------
// Launch. Inputs: x, h0, kz, kr, kh, mz, mr, bz, br. Output: [B, T, H] fp32.
// ---------------------------------------------------------------------------
extern "C" void kernel_launch(void* const* d_in, const int* in_sizes, int n_in,
                              void* d_out, int out_size)
{
    const float* x  = (const float*)d_in[0];
    const float* h0 = (const float*)d_in[1];
    const float* kz = (const float*)d_in[2];
    const float* kr = (const float*)d_in[3];
    const float* kh = (const float*)d_in[4];
    const float* mz = (const float*)d_in[5];
    const float* mr = (const float*)d_in[6];
    const float* bz = (const float*)d_in[7];
    const float* br = (const float*)d_in[8];
    float* out = (float*)d_out;

    cudaFuncSetAttribute(brc_fused, cudaFuncAttributeMaxDynamicSharedMemorySize,
                         FSMEM);

    cvt_x_kernel<<<(MM * KK / 8) / 256, 256>>>(x);
    cvt_w_kernel<<<dim3(16, 16, 3), dim3(32, 8)>>>(kz, kr, kh);

    brc_fused<<<BB * 2, 256, FSMEM>>>(h0, mz, mr, bz, br, out);
}